// round 6
// baseline (speedup 1.0000x reference)
#include <cuda_runtime.h>
#include <cuda_fp16.h>
#include <cstdint>

#define HW 4096
#define DDIM 64
#define NSLICE 256          // total K slices of 16
#define HSLICE 128          // slices per K-half
#define CS_STRIDE 66

// B fragments, lane-major: g_fp[gs][q][lane][4 x b32]; uint4 index = gs*128 + q*32 + lane
// component c of uint4 q: frag j = q*2 + (c>>1), pair = c&1
// K-permutation (matches float4 A loads): real k = (l&3)*4 + pair*2
__device__ uint32_t g_fp[NSLICE * 4 * 32 * 4];

// ---------------------------------------------------------------------------
// Kernel 1: build packed B fragments of f[m,d] = cos(8pi*(w0*gx + w1*gy + b))
// ---------------------------------------------------------------------------
__global__ void pos_enc_kernel(const float* __restrict__ w,
                               const float* __restrict__ bias) {
    int idx = blockIdx.x * blockDim.x + threadIdx.x;
    if (idx >= NSLICE * 512) return;
    int c    = idx & 3;
    int l    = (idx >> 2) & 31;
    int q    = (idx >> 7) & 3;
    int gs   = idx >> 9;
    int j    = q * 2 + (c >> 1);
    int pair = c & 1;
    int d    = j * 8 + (l >> 2);
    int k    = (l & 3) * 4 + pair * 2;
    int m0   = gs * 16 + k;
    float w0 = w[2 * d], w1 = w[2 * d + 1], bd = bias[d];
    float v[2];
#pragma unroll
    for (int t = 0; t < 2; t++) {
        int m = m0 + t;
        int x = m & 63, y = m >> 6;
        float gx = (float)(2 * x - 63) * (1.0f / 64.0f);
        float gy = (float)(2 * y - 63) * (1.0f / 64.0f);
        v[t] = cosf(25.132741228718345f * fmaf(w0, gx, fmaf(w1, gy, bd)));
    }
    __half2 h = __floats2half2_rn(v[0], v[1]);
    g_fp[idx] = *reinterpret_cast<uint32_t*>(&h);
}

// ---------------------------------------------------------------------------
static __device__ __forceinline__ uint32_t e2p(float a, float b) {
    __half2 h = __floats2half2_rn(__expf(a), __expf(b));
    return *reinterpret_cast<uint32_t*>(&h);
}

#define MMA(dst, a0, a1, a2, a3, b0, b1)                                        \
    asm volatile("mma.sync.aligned.m16n8k16.row.col.f32.f16.f16.f32 "           \
                 "{%0,%1,%2,%3},{%4,%5,%6,%7},{%8,%9},{%0,%1,%2,%3};"           \
                 : "+f"(dst[0]), "+f"(dst[1]), "+f"(dst[2]), "+f"(dst[3])       \
                 : "r"(a0), "r"(a1), "r"(a2), "r"(a3), "r"(b0), "r"(b1))

#define LA(st, s)                                                               \
    do { const float* _p = pA + (size_t)(s) * 16;                               \
        A[st][0] = __ldcs((const float4*)_p);                                   \
        A[st][1] = __ldcs((const float4*)(_p + 8 * HW)); } while (0)

#define LB(st, s)                                                               \
    do { const uint4* _p = pB + (size_t)(s) * 128;                              \
        Bv[st][0] = __ldg(_p);      Bv[st][1] = __ldg(_p + 32);                 \
        Bv[st][2] = __ldg(_p + 64); Bv[st][3] = __ldg(_p + 96); } while (0)

// One slice: exp-convert A, prefetch A (dist 2), MMAs on prefetched B, prefetch B (dist 2)
#define STAGE(st, sidx)                                                         \
    do {                                                                        \
        uint32_t ra0 = e2p(A[st][0].x, A[st][0].y);                             \
        uint32_t ra2 = e2p(A[st][0].z, A[st][0].w);                             \
        uint32_t ra1 = e2p(A[st][1].x, A[st][1].y);                             \
        uint32_t ra3 = e2p(A[st][1].z, A[st][1].w);                             \
        if ((sidx) + 2 < HSLICE) LA(st, (sidx) + 2);                            \
        const uint32_t* bp = (const uint32_t*)Bv[st];                           \
        MMA(acc[0], ra0, ra1, ra2, ra3, bp[0],  bp[1]);                         \
        MMA(acc[1], ra0, ra1, ra2, ra3, bp[2],  bp[3]);                         \
        MMA(acc[2], ra0, ra1, ra2, ra3, bp[4],  bp[5]);                         \
        MMA(acc[3], ra0, ra1, ra2, ra3, bp[6],  bp[7]);                         \
        MMA(acc[4], ra0, ra1, ra2, ra3, bp[8],  bp[9]);                         \
        MMA(acc[5], ra0, ra1, ra2, ra3, bp[10], bp[11]);                        \
        MMA(acc[6], ra0, ra1, ra2, ra3, bp[12], bp[13]);                        \
        MMA(acc[7], ra0, ra1, ra2, ra3, bp[14], bp[15]);                        \
        MMA(acc[8], ra0, ra1, ra2, ra3, bz, bz);                                \
        if ((sidx) + 2 < HSLICE) LB(st, (sidx) + 2);                            \
    } while (0)

// ---------------------------------------------------------------------------
// Kernel 2: 8 warps = 4 row-groups x 2 K-halves. Warp: 16 rows x 64 N x K=2048.
// 2-deep A + 2-deep B register pipelines; no smem/barriers in mainloop.
// ---------------------------------------------------------------------------
__global__ __launch_bounds__(256, 2)
void gp_kernel(const float* __restrict__ sim, float* __restrict__ out) {
    __shared__ float Cs[64][CS_STRIDE];
    __shared__ float Zs[64];
    __shared__ float Zr[64];

    const int tid = threadIdx.x;
    const int l   = tid & 31;
    const int w   = tid >> 5;
    const int wm  = w & 3;       // row group
    const int kh  = w >> 2;      // K half
    const int bb  = blockIdx.y;
    const int row0 = blockIdx.x * 64;

    const float* pA = sim + ((size_t)bb * HW + row0 + wm * 16 + (l >> 2)) * (size_t)HW
                          + kh * (HSLICE * 16) + (l & 3) * 4;
    const uint4* pB = ((const uint4*)g_fp) + (size_t)kh * HSLICE * 128 + l;

    float acc[9][4];
#pragma unroll
    for (int i = 0; i < 9; i++)
#pragma unroll
        for (int k = 0; k < 4; k++) acc[i][k] = 0.0f;

    const uint32_t bz = (l < 4) ? 0x3C003C00u : 0u;  // ones in B col n=0

    float4 A[2][2];
    uint4  Bv[2][4];
    LA(0, 0); LB(0, 0);
    LA(1, 1); LB(1, 1);

#pragma unroll 1
    for (int s = 0; s < HSLICE; s += 2) {
        STAGE(0, s);
        STAGE(1, s + 1);
    }

    // ---- epilogue: merge K-halves via smem, divide by Z, coalesced store ----
    const int lr = wm * 16 + (l >> 2);
    if (kh == 0) {
#pragma unroll
        for (int j = 0; j < 8; j++) {
            const int c0 = j * 8 + (l & 3) * 2;
            *(float2*)&Cs[lr][c0]     = make_float2(acc[j][0], acc[j][1]);
            *(float2*)&Cs[lr + 8][c0] = make_float2(acc[j][2], acc[j][3]);
        }
        if ((l & 3) == 0) { Zs[lr] = acc[8][0]; Zs[lr + 8] = acc[8][2]; }
    }
    __syncthreads();
    if (kh == 1) {
#pragma unroll
        for (int j = 0; j < 8; j++) {
            const int c0 = j * 8 + (l & 3) * 2;
            Cs[lr][c0]         += acc[j][0];
            Cs[lr][c0 + 1]     += acc[j][1];
            Cs[lr + 8][c0]     += acc[j][2];
            Cs[lr + 8][c0 + 1] += acc[j][3];
        }
        if ((l & 3) == 0) { Zs[lr] += acc[8][0]; Zs[lr + 8] += acc[8][2]; }
    }
    __syncthreads();
    if (tid < 64) Zr[tid] = 1.0f / Zs[tid];
    __syncthreads();

    {
        const int d = tid >> 2, seg = tid & 3;
        float* go = out + ((size_t)(bb * DDIM + d)) * HW + row0 + seg * 16;
#pragma unroll
        for (int i = 0; i < 4; i++) {
            const int n = seg * 16 + i * 4;
            float4 o;
            o.x = Cs[n + 0][d] * Zr[n + 0];
            o.y = Cs[n + 1][d] * Zr[n + 1];
            o.z = Cs[n + 2][d] * Zr[n + 2];
            o.w = Cs[n + 3][d] * Zr[n + 3];
            *(float4*)(go + i * 4) = o;
        }
    }
}

// ---------------------------------------------------------------------------
extern "C" void kernel_launch(void* const* d_in, const int* in_sizes, int n_in,
                              void* d_out, int out_size) {
    const float* sim  = (const float*)d_in[0];  // [4, 4096, 4096] fp32
    const float* w    = (const float*)d_in[1];  // [64, 2] fp32
    const float* bias = (const float*)d_in[2];  // [64] fp32
    float* out = (float*)d_out;                 // [4, 64, 64, 64] fp32

    pos_enc_kernel<<<(NSLICE * 512 + 255) / 256, 256>>>(w, bias);

    dim3 grid(HW / 64, 4);
    gp_kernel<<<grid, 256>>>(sim, out);
}